// round 7
// baseline (speedup 1.0000x reference)
#include <cuda_runtime.h>

// ---------------- problem constants ----------------
#define NN 10000
#define LL 256
#define EE 160000
#define HH 64
#define DM 4
#define DS 32
#define DC 4
#define DI 8
#define NLAYERS 8
#define EPSV 1e-6f

// ---------------- scratch (device globals; no allocation) ----------------
__device__ float g_h[NN * HH];          // node features
__device__ float g_e[EE * HH];          // edge features (updated in place)
__device__ float g_hw[NN * 5 * HH];     // A1|A2|A3|B1|B2 per node (reused by pred)
__device__ float g_x2[NN * DM];
__device__ int g_deg_in[NN], g_deg_out[NN];
__device__ int g_ofs_in[NN + 1], g_ofs_out[NN + 1];
__device__ int g_cur_in[NN], g_cur_out[NN];
__device__ int g_csr_in[EE], g_csr_out[EE];
__device__ int g_order[NN];

__device__ __forceinline__ float sigmoidf_(float x) {
    return 1.f / (1.f + __expf(-x));
}

// ---------------- CSR build ----------------
__global__ void k_zero_deg() {
    int i = blockIdx.x * blockDim.x + threadIdx.x;
    if (i < NN) { g_deg_in[i] = 0; g_deg_out[i] = 0; }
}

__global__ void k_hist(const int* __restrict__ src, const int* __restrict__ dst) {
    int i = blockIdx.x * blockDim.x + threadIdx.x;
    if (i < EE) {
        atomicAdd(&g_deg_in[dst[i]], 1);
        atomicAdd(&g_deg_out[src[i]], 1);
    }
}

__global__ void k_scan() {
    __shared__ int part[1024];
    int t = threadIdx.x;
    for (int pass = 0; pass < 2; pass++) {
        const int* deg = pass ? g_deg_out : g_deg_in;
        int* ofs = pass ? g_ofs_out : g_ofs_in;
        int* cur = pass ? g_cur_out : g_cur_in;
        int lo = t * 10;
        int hi = lo + 10; if (hi > NN) hi = NN;
        int s = 0;
        for (int i = lo; i < hi && i < NN; i++) s += deg[i];
        part[t] = s;
        __syncthreads();
        for (int d = 1; d < 1024; d <<= 1) {
            int add = (t >= d) ? part[t - d] : 0;
            __syncthreads();
            part[t] += add;
            __syncthreads();
        }
        int run = part[t] - s;  // exclusive base
        for (int i = lo; i < hi && i < NN; i++) {
            ofs[i] = run; cur[i] = run; run += deg[i];
        }
        if (lo < NN && hi == NN) ofs[NN] = run;
        __syncthreads();
    }
}

__global__ void k_fill(const int* __restrict__ src, const int* __restrict__ dst) {
    int i = blockIdx.x * blockDim.x + threadIdx.x;
    if (i < EE) {
        int p = atomicAdd(&g_cur_in[dst[i]], 1);
        g_csr_in[p] = i;
        int q = atomicAdd(&g_cur_out[src[i]], 1);
        g_csr_out[q] = i;
    }
}

// deterministic order: warp-bitonic sort of each node's edge-id segment (len<=64 fast path)
__global__ void k_sortcsr() {
    int gw = (blockIdx.x * blockDim.x + threadIdx.x) >> 5;
    int lane = threadIdx.x & 31;
    if (gw >= 2 * NN) return;
    int n = (gw < NN) ? gw : gw - NN;
    int* csr = (gw < NN) ? g_csr_in : g_csr_out;
    const int* ofs = (gw < NN) ? g_ofs_in : g_ofs_out;
    int beg = ofs[n], end = ofs[n + 1];
    int len = end - beg;
    if (len <= 1) return;
    if (len <= 64) {
        const int INF = 0x7fffffff;
        int a = (lane < len) ? csr[beg + lane] : INF;
        int b = (32 + lane < len) ? csr[beg + 32 + lane] : INF;
#pragma unroll
        for (int k = 2; k <= 64; k <<= 1) {
#pragma unroll
            for (int j = 32; j > 0; j >>= 1) {
                if (j >= k) continue;
                if (j == 32) {
                    int lo = min(a, b), hi = max(a, b);
                    a = lo; b = hi;
                } else {
                    int pa = __shfl_xor_sync(0xffffffffu, a, j);
                    bool upa = ((lane & j) == 0);
                    bool asca = ((lane & k) == 0);
                    a = (upa == asca) ? min(a, pa) : max(a, pa);
                    int pb = __shfl_xor_sync(0xffffffffu, b, j);
                    int idxb = lane + 32;
                    bool upb = ((idxb & j) == 0);
                    bool ascb = ((idxb & k) == 0);
                    b = (upb == ascb) ? min(b, pb) : max(b, pb);
                }
            }
        }
        if (lane < len) csr[beg + lane] = a;
        if (32 + lane < len) csr[beg + 32 + lane] = b;
    } else {
        if (lane == 0) {
            for (int i = beg + 1; i < end; i++) {
                int key = csr[i]; int j = i - 1;
                while (j >= beg && csr[j] > key) { csr[j + 1] = csr[j]; j--; }
                csr[j + 1] = key;
            }
        }
    }
}

// ---------------- read_length binning: fused hist+scan+place, descending rl (LPT) ----------------
__global__ void k_rlscanplace(const int* __restrict__ rl) {
    __shared__ int sbin[LL];
    __shared__ int sofs[LL];
    int t = threadIdx.x;  // 256
    sbin[t] = 0;
    __syncthreads();
    for (int i = t; i < NN; i += 256) atomicAdd(&sbin[rl[i] - 1], 1);
    __syncthreads();
    int v = sbin[t];
    for (int d = 1; d < LL; d <<= 1) {
        int add = (t >= d) ? sbin[t - d] : 0;
        __syncthreads();
        sbin[t] += add;
        __syncthreads();
    }
    sofs[t] = sbin[t] - v;  // exclusive (ascending)
    __syncthreads();
    for (int i = t; i < NN; i += 256) {
        int pos = atomicAdd(&sofs[rl[i] - 1], 1);
        g_order[NN - 1 - pos] = i;   // descending rl -> LPT scheduling
    }
}

// ---------------- mamba: warp per node (rl-sorted desc), lane = state index ----------------
__global__ void k_mamba(const float* __restrict__ reads, const int* __restrict__ read_length,
                        const float* __restrict__ in_proj_W, const float* __restrict__ conv_W,
                        const float* __restrict__ conv_b, const float* __restrict__ x_proj_W,
                        const float* __restrict__ dt_proj_W, const float* __restrict__ dt_proj_b,
                        const float* __restrict__ A_log, const float* __restrict__ Dskip,
                        const float* __restrict__ out_proj_W) {
    __shared__ float op[32];
    __shared__ float ys[8][8], os[8][8];
    int tid = threadIdx.x;
    if (tid < 32) op[tid] = out_proj_W[tid];
    __syncthreads();
    int warp = tid >> 5, lane = tid & 31;
    int idx = blockIdx.x * 8 + warp;
    if (idx >= NN) return;
    int li = lane & 7;

    float ipx[4], ipz[4], cwr[4];
#pragma unroll
    for (int m = 0; m < 4; m++) {
        ipx[m] = __ldg(&in_proj_W[m * 16 + li]);
        ipz[m] = __ldg(&in_proj_W[m * 16 + 8 + li]);
        cwr[m] = __ldg(&conv_W[li * 4 + m]);
    }
    float cbr = __ldg(&conv_b[li]);
    float dtwr = __ldg(&dt_proj_W[li]);
    float dtbr = __ldg(&dt_proj_b[li]);
    float dskr = __ldg(&Dskip[li]);
    float xp0r[8], xpBr[8], xpCr[8], Asr[8];
#pragma unroll
    for (int i = 0; i < 8; i++) {
        xp0r[i] = __ldg(&x_proj_W[i * 65]);
        xpBr[i] = __ldg(&x_proj_W[i * 65 + 1 + lane]);
        xpCr[i] = __ldg(&x_proj_W[i * 65 + 33 + lane]);
        Asr[i] = -__expf(__ldg(&A_log[i * 32 + lane]));
    }

    int n = g_order[idx];
    int rl = read_length[n];
    float hst[8];
#pragma unroll
    for (int i = 0; i < 8; i++) hst[i] = 0.f;
    float c0 = 0.f, c1 = 0.f, c2 = 0.f;
    float xc = 0.f, zf = 0.f, CsLast = 0.f;
    const float4* rd4 = (const float4*)(reads + (size_t)n * LL * 4);
    float4 rd = rd4[0];

    for (int t = 0; t < rl; t++) {
        int tn = (t + 1 < rl) ? (t + 1) : t;
        float4 nxt = rd4[tn];                          // prefetch
        float xh = rd.x * ipx[0] + rd.y * ipx[1] + rd.z * ipx[2] + rd.w * ipx[3];
        float c = c0 * cwr[0] + c1 * cwr[1] + c2 * cwr[2] + xh * cwr[3] + cbr;
        c0 = c1; c1 = c2; c2 = xh;
        xc = c * sigmoidf_(c);
        if (t == rl - 1)
            zf = rd.x * ipz[0] + rd.y * ipz[1] + rd.z * ipz[2] + rd.w * ipz[3];

        float xr[8];
        float dbl0 = 0.f, Bs = 0.f, Cs = 0.f;
#pragma unroll
        for (int i = 0; i < 8; i++) {
            float xi = __shfl_sync(0xffffffffu, xc, i);
            xr[i] = xi;
            dbl0 += xi * xp0r[i];
            Bs += xi * xpBr[i];
            Cs += xi * xpCr[i];
        }
        float dr = dbl0 * dtwr + dtbr;
        float dtv = (dr > 15.f) ? dr : __logf(1.f + __expf(dr));
#pragma unroll
        for (int i = 0; i < 8; i++) {
            float dti = __shfl_sync(0xffffffffu, dtv, i);
            hst[i] = __expf(dti * Asr[i]) * hst[i] + (dti * Bs) * xr[i];
        }
        if (t == rl - 1) CsLast = Cs;
        rd = nxt;
    }
#pragma unroll
    for (int i = 0; i < 8; i++) {
        float v = hst[i] * CsLast;
#pragma unroll
        for (int off = 16; off; off >>= 1) v += __shfl_xor_sync(0xffffffffu, v, off);
        if (lane == 0) ys[warp][i] = v;
    }
    __syncwarp();
    if (lane < 8) {
        float y = ys[warp][lane] + xc * dskr;
        os[warp][lane] = y * (zf * sigmoidf_(zf));
    }
    __syncwarp();
    if (lane < 4) {
        float acc = 0.f;
#pragma unroll
        for (int i = 0; i < 8; i++) acc += os[warp][i] * op[i * 4 + lane];
        g_x2[n * 4 + lane] = acc;
    }
}

// ---------------- encoders ----------------
__global__ void k_enc(const float* __restrict__ in, const float* __restrict__ W1,
                      const float* __restrict__ b1, const float* __restrict__ W2,
                      const float* __restrict__ b2, int rows, int target_e) {
    float* outp = target_e ? g_e : g_h;
    int tid = threadIdx.x;
    int j = tid & 63, g = tid >> 6;
    float w1a[16], w1b[16], bb1[16], w2c[16];
#pragma unroll
    for (int i = 0; i < 16; i++) {
        w1a[i] = W1[i];
        w1b[i] = W1[16 + i];
        bb1[i] = b1[i];
        w2c[i] = W2[i * 64 + j];
    }
    float b2j = b2[j];
    for (int r = blockIdx.x * 4 + g; r < rows; r += gridDim.x * 4) {
        float x0 = in[r * 2], x1 = in[r * 2 + 1];
        float acc = b2j;
#pragma unroll
        for (int i = 0; i < 16; i++) {
            float hid = fmaxf(x0 * w1a[i] + x1 * w1b[i] + bb1[i], 0.f);
            acc += hid * w2c[i];
        }
        outp[r * 64 + j] = acc;
    }
}

// ---------------- per-layer node GEMM: g_hw = h @ [W0..W4] + b (smem staged) ----------------
__global__ void k_hw(const float* __restrict__ gnn_W, const float* __restrict__ gnn_b, int l) {
    __shared__ float hs[4][64];
    int tid = threadIdx.x;       // 320 threads
    int m = tid >> 6, j = tid & 63;
    const float* Wm = gnn_W + (size_t)(l * 6 + m) * 4096;
    float w[64];
#pragma unroll
    for (int k = 0; k < 64; k++) w[k] = Wm[k * 64 + j];
    float bias = gnn_b[(l * 6 + m) * 64 + j];
    for (int nb = blockIdx.x * 4; nb < NN; nb += gridDim.x * 4) {
        __syncthreads();
        if (tid < 256) {
            int nn = nb + (tid >> 6);
            hs[tid >> 6][tid & 63] = (nn < NN) ? g_h[nn * 64 + (tid & 63)] : 0.f;
        }
        __syncthreads();
#pragma unroll
        for (int b = 0; b < 4; b++) {
            int nn = nb + b;
            if (nn >= NN) break;
            const float4* h4 = (const float4*)hs[b];
            float a0 = bias, a1 = 0.f, a2 = 0.f, a3 = 0.f;
#pragma unroll
            for (int k4 = 0; k4 < 16; k4 += 4) {
                float4 v0 = h4[k4], v1 = h4[k4 + 1], v2 = h4[k4 + 2], v3 = h4[k4 + 3];
                a0 += v0.x * w[4 * k4 + 0] + v0.y * w[4 * k4 + 1] + v0.z * w[4 * k4 + 2] + v0.w * w[4 * k4 + 3];
                a1 += v1.x * w[4 * k4 + 4] + v1.y * w[4 * k4 + 5] + v1.z * w[4 * k4 + 6] + v1.w * w[4 * k4 + 7];
                a2 += v2.x * w[4 * k4 + 8] + v2.y * w[4 * k4 + 9] + v2.z * w[4 * k4 + 10] + v2.w * w[4 * k4 + 11];
                a3 += v3.x * w[4 * k4 + 12] + v3.y * w[4 * k4 + 13] + v3.z * w[4 * k4 + 14] + v3.w * w[4 * k4 + 15];
            }
            g_hw[(size_t)nn * 320 + m * 64 + j] = (a0 + a1) + (a2 + a3);
        }
    }
}

// ---------------- per-layer edge update, k-split: pair of threads per (edge, channel) ----------------
// tid = g*128 + j*2 + h : g = edge-in-tile [0,4), j = channel [0,64), h = k-half [0,2)
__global__ void __launch_bounds__(512, 2)
k_edge(const int* __restrict__ src, const int* __restrict__ dst,
       const float* __restrict__ gnn_W, const float* __restrict__ gnn_b, int l) {
    __shared__ float es[4][64];
    int tid = threadIdx.x;   // 512
    int g = tid >> 7;
    int r = tid & 127;
    int j = r >> 1;
    int h = r & 1;
    const float* W5 = gnn_W + (size_t)(l * 6 + 5) * 4096 + (size_t)h * 32 * 64;
    float w[32];
#pragma unroll
    for (int k = 0; k < 32; k++) w[k] = W5[k * 64 + j];
    float b5 = gnn_b[(l * 6 + 5) * 64 + j];
    for (int base = blockIdx.x * 4; base < EE; base += gridDim.x * 4) {
        int eg = base + g;
        bool valid = (eg < EE);
        __syncthreads();
        if (r < 64) es[g][r] = valid ? g_e[(size_t)eg * 64 + r] : 0.f;
        __syncthreads();
        float hb = 0.f;
        if (valid && h == 0) {
            int s = src[eg], d = dst[eg];
            hb = g_hw[(size_t)s * 320 + 192 + j] + g_hw[(size_t)d * 320 + 256 + j];
        }
        const float4* e4 = (const float4*)(es[g] + h * 32);
        float a0 = 0.f, a1 = 0.f;
#pragma unroll
        for (int k4 = 0; k4 < 8; k4 += 2) {
            float4 v0 = e4[k4], v1 = e4[k4 + 1];
            a0 += v0.x * w[4 * k4 + 0] + v0.y * w[4 * k4 + 1] + v0.z * w[4 * k4 + 2] + v0.w * w[4 * k4 + 3];
            a1 += v1.x * w[4 * k4 + 4] + v1.y * w[4 * k4 + 5] + v1.z * w[4 * k4 + 6] + v1.w * w[4 * k4 + 7];
        }
        float acc = a0 + a1;
        acc += __shfl_xor_sync(0xffffffffu, acc, 1);   // combine k-halves
        if (valid && h == 0) {
            float v = acc + hb + b5;
            g_e[(size_t)eg * 64 + j] = es[g][j] + fmaxf(v, 0.f);
        }
    }
}

// ---------------- fused aggregation + h update: block per node, 128 threads ----------------
__global__ void k_agg(const int* __restrict__ src, const int* __restrict__ dst) {
    __shared__ float sf[64], sb[64];
    int n = blockIdx.x;
    int tid = threadIdx.x;  // 128
    bool fwd = tid < 64;
    int j = tid & 63;
    const int* ofs = fwd ? g_ofs_in : g_ofs_out;
    const int* csr = fwd ? g_csr_in : g_csr_out;
    const int* oth = fwd ? src : dst;
    int off = fwd ? 64 : 128;
    int beg = ofs[n], end = ofs[n + 1];
    float num = 0.f, den = 0.f;
    int p = beg;
    for (; p + 3 < end; p += 4) {
        int e0 = csr[p], e1 = csr[p + 1], e2 = csr[p + 2], e3 = csr[p + 3];
        int o0 = oth[e0], o1 = oth[e1], o2 = oth[e2], o3 = oth[e3];
        float v0 = __ldg(&g_e[(size_t)e0 * 64 + j]);
        float v1 = __ldg(&g_e[(size_t)e1 * 64 + j]);
        float v2 = __ldg(&g_e[(size_t)e2 * 64 + j]);
        float v3 = __ldg(&g_e[(size_t)e3 * 64 + j]);
        float h0 = __ldg(&g_hw[(size_t)o0 * 320 + off + j]);
        float h1 = __ldg(&g_hw[(size_t)o1 * 320 + off + j]);
        float h2 = __ldg(&g_hw[(size_t)o2 * 320 + off + j]);
        float h3 = __ldg(&g_hw[(size_t)o3 * 320 + off + j]);
        float s0 = sigmoidf_(v0), s1 = sigmoidf_(v1), s2 = sigmoidf_(v2), s3 = sigmoidf_(v3);
        num += s0 * h0 + s1 * h1 + s2 * h2 + s3 * h3;
        den += (s0 + s1) + (s2 + s3);
    }
    for (; p < end; p++) {
        int e0 = csr[p];
        int o0 = oth[e0];
        float s0 = sigmoidf_(__ldg(&g_e[(size_t)e0 * 64 + j]));
        num += s0 * __ldg(&g_hw[(size_t)o0 * 320 + off + j]);
        den += s0;
    }
    (fwd ? sf : sb)[j] = num / (den + EPSV);
    __syncthreads();
    if (tid < 64) {
        float v = g_hw[(size_t)n * 320 + j] + sf[j] + sb[j];
        g_h[n * 64 + j] += fmaxf(v, 0.f);
    }
}

// ---------------- h += x2 @ base_W + base_b ----------------
__global__ void k_base(const float* __restrict__ base_W, const float* __restrict__ base_b) {
    int idx = blockIdx.x * blockDim.x + threadIdx.x;
    if (idx < NN * 64) {
        int n = idx >> 6, j = idx & 63;
        float v = g_x2[n * 4 + 0] * base_W[j] + g_x2[n * 4 + 1] * base_W[64 + j]
                + g_x2[n * 4 + 2] * base_W[128 + j] + g_x2[n * 4 + 3] * base_W[192 + j] + base_b[j];
        g_h[idx] += v;
    }
}

// ---------------- prediction head, stage 1: per-node projections (smem staged) ----------------
__global__ void k_prednode(const float* __restrict__ Wp1) {
    __shared__ float hs[4][64];
    int tid = threadIdx.x;   // 128 = 2 groups of 64
    int m = tid >> 6, j = tid & 63;
    const float* Wm = Wp1 + (size_t)m * 64 * 64;
    float w[64];
#pragma unroll
    for (int k = 0; k < 64; k++) w[k] = Wm[k * 64 + j];
    for (int nb = blockIdx.x * 4; nb < NN; nb += gridDim.x * 4) {
        __syncthreads();
        {
            int nn = nb + (tid >> 6);
            hs[tid >> 6][j] = (nn < NN) ? g_h[nn * 64 + j] : 0.f;
            int nn2 = nb + 2 + (tid >> 6);
            hs[2 + (tid >> 6)][j] = (nn2 < NN) ? g_h[nn2 * 64 + j] : 0.f;
        }
        __syncthreads();
#pragma unroll
        for (int b = 0; b < 4; b++) {
            int nn = nb + b;
            if (nn >= NN) break;
            const float4* h4 = (const float4*)hs[b];
            float a0 = 0.f, a1 = 0.f, a2 = 0.f, a3 = 0.f;
#pragma unroll
            for (int k4 = 0; k4 < 16; k4 += 4) {
                float4 v0 = h4[k4], v1 = h4[k4 + 1], v2 = h4[k4 + 2], v3 = h4[k4 + 3];
                a0 += v0.x * w[4 * k4 + 0] + v0.y * w[4 * k4 + 1] + v0.z * w[4 * k4 + 2] + v0.w * w[4 * k4 + 3];
                a1 += v1.x * w[4 * k4 + 4] + v1.y * w[4 * k4 + 5] + v1.z * w[4 * k4 + 6] + v1.w * w[4 * k4 + 7];
                a2 += v2.x * w[4 * k4 + 8] + v2.y * w[4 * k4 + 9] + v2.z * w[4 * k4 + 10] + v2.w * w[4 * k4 + 11];
                a3 += v3.x * w[4 * k4 + 12] + v3.y * w[4 * k4 + 13] + v3.z * w[4 * k4 + 14] + v3.w * w[4 * k4 + 15];
            }
            g_hw[(size_t)nn * 320 + m * 64 + j] = (a0 + a1) + (a2 + a3);
        }
    }
}

// ---------------- prediction head, stage 2: per-edge, k-split ----------------
__global__ void __launch_bounds__(512, 2)
k_prededge(const int* __restrict__ src, const int* __restrict__ dst,
           const float* __restrict__ Wp1, const float* __restrict__ bp1,
           const float* __restrict__ Wp2, const float* __restrict__ bp2,
           float* __restrict__ out) {
    __shared__ float es[4][64];
    __shared__ float red[4][4];
    int tid = threadIdx.x;   // 512
    int g = tid >> 7;
    int r = tid & 127;
    int j = r >> 1;
    int h = r & 1;
    int warp = tid >> 5;          // 16 warps; 4 warps per edge
    int wsub = warp & 3;          // warp within edge
    const float* Wc = Wp1 + (size_t)128 * 64 + (size_t)h * 32 * 64;
    float w[32];
#pragma unroll
    for (int k = 0; k < 32; k++) w[k] = Wc[k * 64 + j];
    float bp1j = bp1[j];
    float wp2j = Wp2[j];
    float bp2v = bp2[0];
    for (int base = blockIdx.x * 4; base < EE; base += gridDim.x * 4) {
        int eg = base + g;
        bool valid = (eg < EE);
        __syncthreads();
        if (r < 64) es[g][r] = valid ? g_e[(size_t)eg * 64 + r] : 0.f;
        __syncthreads();
        float hb = 0.f;
        if (valid && h == 0) {
            int s = src[eg], d = dst[eg];
            hb = g_hw[(size_t)s * 320 + j] + g_hw[(size_t)d * 320 + 64 + j];
        }
        const float4* e4 = (const float4*)(es[g] + h * 32);
        float a0 = 0.f, a1 = 0.f;
#pragma unroll
        for (int k4 = 0; k4 < 8; k4 += 2) {
            float4 v0 = e4[k4], v1 = e4[k4 + 1];
            a0 += v0.x * w[4 * k4 + 0] + v0.y * w[4 * k4 + 1] + v0.z * w[4 * k4 + 2] + v0.w * w[4 * k4 + 3];
            a1 += v1.x * w[4 * k4 + 4] + v1.y * w[4 * k4 + 5] + v1.z * w[4 * k4 + 6] + v1.w * w[4 * k4 + 7];
        }
        float acc = a0 + a1;
        acc += __shfl_xor_sync(0xffffffffu, acc, 1);   // combine k-halves
        // per-channel relu*wp2; odd lanes contribute 0, then full-warp sum
        float p = (h == 0 && valid) ? fmaxf(acc + hb + bp1j, 0.f) * wp2j : 0.f;
#pragma unroll
        for (int off = 16; off > 1; off >>= 1) p += __shfl_xor_sync(0xffffffffu, p, off);
        p += __shfl_xor_sync(0xffffffffu, p, 1);
        if ((tid & 31) == 0) red[g][wsub] = p;
        __syncthreads();
        if (r == 0 && valid)
            out[eg] = (red[g][0] + red[g][1]) + (red[g][2] + red[g][3]) + bp2v;
    }
}

// ---------------- launch ----------------
extern "C" void kernel_launch(void* const* d_in, const int* in_sizes, int n_in,
                              void* d_out, int out_size) {
    const float* x        = (const float*)d_in[0];
    const float* e_in     = (const float*)d_in[1];
    const float* reads    = (const float*)d_in[2];
    const int*   src      = (const int*)d_in[3];
    const int*   dst      = (const int*)d_in[4];
    const int*   rl       = (const int*)d_in[5];
    const float* W1n      = (const float*)d_in[6];
    const float* b1n      = (const float*)d_in[7];
    const float* W2n      = (const float*)d_in[8];
    const float* b2n      = (const float*)d_in[9];
    const float* W1e      = (const float*)d_in[10];
    const float* b1e      = (const float*)d_in[11];
    const float* W2e      = (const float*)d_in[12];
    const float* b2e      = (const float*)d_in[13];
    const float* gnn_W    = (const float*)d_in[14];
    const float* gnn_b    = (const float*)d_in[15];
    const float* in_projW = (const float*)d_in[16];
    const float* conv_W   = (const float*)d_in[17];
    const float* conv_b   = (const float*)d_in[18];
    const float* x_projW  = (const float*)d_in[19];
    const float* dt_projW = (const float*)d_in[20];
    const float* dt_projb = (const float*)d_in[21];
    const float* A_log    = (const float*)d_in[22];
    const float* Dskip    = (const float*)d_in[23];
    const float* out_projW= (const float*)d_in[24];
    const float* base_W   = (const float*)d_in[25];
    const float* base_b   = (const float*)d_in[26];
    const float* Wp1      = (const float*)d_in[27];
    const float* bp1      = (const float*)d_in[28];
    const float* Wp2      = (const float*)d_in[29];
    const float* bp2      = (const float*)d_in[30];
    float* out = (float*)d_out;

    static cudaStream_t s1 = nullptr, s2 = nullptr;
    static cudaEvent_t evFork = nullptr, evCsr = nullptr, evMamba = nullptr;
    if (s1 == nullptr) {
        cudaStreamCreateWithFlags(&s1, cudaStreamNonBlocking);
        cudaStreamCreateWithFlags(&s2, cudaStreamNonBlocking);
        cudaEventCreateWithFlags(&evFork, cudaEventDisableTiming);
        cudaEventCreateWithFlags(&evCsr, cudaEventDisableTiming);
        cudaEventCreateWithFlags(&evMamba, cudaEventDisableTiming);
    }

    // main stream: first 4 kernels (idx 3 = k-split k_edge l0 -> ncu sample)
    k_enc<<<512, 256>>>(x, W1n, b1n, W2n, b2n, NN, 0);               // 0
    k_enc<<<2048, 256>>>(e_in, W1e, b1e, W2e, b2e, EE, 1);           // 1
    k_hw<<<1250, 320>>>(gnn_W, gnn_b, 0);                            // 2
    k_edge<<<2048, 512>>>(src, dst, gnn_W, gnn_b, 0);                // 3 <- profiled
    cudaEventRecord(evFork, 0);

    // side branch 1: CSR build
    cudaStreamWaitEvent(s1, evFork, 0);
    k_zero_deg<<<(NN + 255) / 256, 256, 0, s1>>>();
    k_hist<<<(EE + 255) / 256, 256, 0, s1>>>(src, dst);
    k_scan<<<1, 1024, 0, s1>>>();
    k_fill<<<(EE + 255) / 256, 256, 0, s1>>>(src, dst);
    k_sortcsr<<<(2 * NN * 32 + 255) / 256, 256, 0, s1>>>();
    cudaEventRecord(evCsr, s1);

    // side branch 2: mamba
    cudaStreamWaitEvent(s2, evFork, 0);
    k_rlscanplace<<<1, 256, 0, s2>>>(rl);
    k_mamba<<<1250, 256, 0, s2>>>(reads, rl, in_projW, conv_W, conv_b,
                                  x_projW, dt_projW, dt_projb, A_log, Dskip, out_projW);
    cudaEventRecord(evMamba, s2);

    // main: layer 0 aggregation needs CSR
    cudaStreamWaitEvent(0, evCsr, 0);
    k_agg<<<NN, 128>>>(src, dst);

    for (int l = 1; l < NLAYERS; l++) {
        k_hw<<<1250, 320>>>(gnn_W, gnn_b, l);
        k_edge<<<2048, 512>>>(src, dst, gnn_W, gnn_b, l);
        k_agg<<<NN, 128>>>(src, dst);
    }

    // base add needs mamba result
    cudaStreamWaitEvent(0, evMamba, 0);
    k_base<<<(NN * 64 + 255) / 256, 256>>>(base_W, base_b);
    k_prednode<<<1250, 128>>>(Wp1);
    k_prededge<<<2048, 512>>>(src, dst, Wp1, bp1, Wp2, bp2, out);
}

// round 8
// speedup vs baseline: 1.9065x; 1.9065x over previous
#include <cuda_runtime.h>

// ---------------- problem constants ----------------
#define NN 10000
#define LL 256
#define EE 160000
#define HH 64
#define DM 4
#define DS 32
#define DC 4
#define DI 8
#define NLAYERS 8
#define EPSV 1e-6f

// ---------------- scratch (device globals; no allocation) ----------------
__device__ float g_h[NN * HH];          // node features
__device__ float g_e[EE * HH];          // edge features (updated in place)
__device__ float g_hw[NN * 5 * HH];     // A1|A2|A3|B1|B2 per node (reused by pred)
__device__ float g_x2[NN * DM];
__device__ int g_deg_in[NN], g_deg_out[NN];
__device__ int g_ofs_in[NN + 1], g_ofs_out[NN + 1];
__device__ int g_cur_in[NN], g_cur_out[NN];
__device__ int g_csr_in[EE], g_csr_out[EE];
__device__ int g_order[NN];

__device__ __forceinline__ float sigmoidf_(float x) {
    return 1.f / (1.f + __expf(-x));
}

// ---------------- CSR build ----------------
__global__ void k_zero_deg() {
    int i = blockIdx.x * blockDim.x + threadIdx.x;
    if (i < NN) { g_deg_in[i] = 0; g_deg_out[i] = 0; }
}

__global__ void k_hist(const int* __restrict__ src, const int* __restrict__ dst) {
    int i = blockIdx.x * blockDim.x + threadIdx.x;
    if (i < EE) {
        atomicAdd(&g_deg_in[dst[i]], 1);
        atomicAdd(&g_deg_out[src[i]], 1);
    }
}

__global__ void k_scan() {
    __shared__ int part[1024];
    int t = threadIdx.x;
    for (int pass = 0; pass < 2; pass++) {
        const int* deg = pass ? g_deg_out : g_deg_in;
        int* ofs = pass ? g_ofs_out : g_ofs_in;
        int* cur = pass ? g_cur_out : g_cur_in;
        int lo = t * 10;
        int hi = lo + 10; if (hi > NN) hi = NN;
        int s = 0;
        for (int i = lo; i < hi && i < NN; i++) s += deg[i];
        part[t] = s;
        __syncthreads();
        for (int d = 1; d < 1024; d <<= 1) {
            int add = (t >= d) ? part[t - d] : 0;
            __syncthreads();
            part[t] += add;
            __syncthreads();
        }
        int run = part[t] - s;  // exclusive base
        for (int i = lo; i < hi && i < NN; i++) {
            ofs[i] = run; cur[i] = run; run += deg[i];
        }
        if (lo < NN && hi == NN) ofs[NN] = run;
        __syncthreads();
    }
}

__global__ void k_fill(const int* __restrict__ src, const int* __restrict__ dst) {
    int i = blockIdx.x * blockDim.x + threadIdx.x;
    if (i < EE) {
        int p = atomicAdd(&g_cur_in[dst[i]], 1);
        g_csr_in[p] = i;
        int q = atomicAdd(&g_cur_out[src[i]], 1);
        g_csr_out[q] = i;
    }
}

// deterministic order: warp-bitonic sort of each node's edge-id segment (len<=64 fast path)
__global__ void k_sortcsr() {
    int gw = (blockIdx.x * blockDim.x + threadIdx.x) >> 5;
    int lane = threadIdx.x & 31;
    if (gw >= 2 * NN) return;
    int n = (gw < NN) ? gw : gw - NN;
    int* csr = (gw < NN) ? g_csr_in : g_csr_out;
    const int* ofs = (gw < NN) ? g_ofs_in : g_ofs_out;
    int beg = ofs[n], end = ofs[n + 1];
    int len = end - beg;
    if (len <= 1) return;
    if (len <= 64) {
        const int INF = 0x7fffffff;
        int a = (lane < len) ? csr[beg + lane] : INF;
        int b = (32 + lane < len) ? csr[beg + 32 + lane] : INF;
#pragma unroll
        for (int k = 2; k <= 64; k <<= 1) {
#pragma unroll
            for (int j = 32; j > 0; j >>= 1) {
                if (j >= k) continue;
                if (j == 32) {
                    int lo = min(a, b), hi = max(a, b);
                    a = lo; b = hi;
                } else {
                    int pa = __shfl_xor_sync(0xffffffffu, a, j);
                    bool upa = ((lane & j) == 0);
                    bool asca = ((lane & k) == 0);
                    a = (upa == asca) ? min(a, pa) : max(a, pa);
                    int pb = __shfl_xor_sync(0xffffffffu, b, j);
                    int idxb = lane + 32;
                    bool upb = ((idxb & j) == 0);
                    bool ascb = ((idxb & k) == 0);
                    b = (upb == ascb) ? min(b, pb) : max(b, pb);
                }
            }
        }
        if (lane < len) csr[beg + lane] = a;
        if (32 + lane < len) csr[beg + 32 + lane] = b;
    } else {
        if (lane == 0) {
            for (int i = beg + 1; i < end; i++) {
                int key = csr[i]; int j = i - 1;
                while (j >= beg && csr[j] > key) { csr[j + 1] = csr[j]; j--; }
                csr[j + 1] = key;
            }
        }
    }
}

// ---------------- read_length binning: fused hist+scan+place, descending rl (LPT) ----------------
__global__ void k_rlscanplace(const int* __restrict__ rl) {
    __shared__ int sbin[LL];
    __shared__ int sofs[LL];
    int t = threadIdx.x;  // 256
    sbin[t] = 0;
    __syncthreads();
    for (int i = t; i < NN; i += 256) atomicAdd(&sbin[rl[i] - 1], 1);
    __syncthreads();
    int v = sbin[t];
    for (int d = 1; d < LL; d <<= 1) {
        int add = (t >= d) ? sbin[t - d] : 0;
        __syncthreads();
        sbin[t] += add;
        __syncthreads();
    }
    sofs[t] = sbin[t] - v;  // exclusive (ascending)
    __syncthreads();
    for (int i = t; i < NN; i += 256) {
        int pos = atomicAdd(&sofs[rl[i] - 1], 1);
        g_order[NN - 1 - pos] = i;   // descending rl -> LPT scheduling
    }
}

// ---------------- mamba: warp per node (rl-sorted desc), lane = state index ----------------
__global__ void k_mamba(const float* __restrict__ reads, const int* __restrict__ read_length,
                        const float* __restrict__ in_proj_W, const float* __restrict__ conv_W,
                        const float* __restrict__ conv_b, const float* __restrict__ x_proj_W,
                        const float* __restrict__ dt_proj_W, const float* __restrict__ dt_proj_b,
                        const float* __restrict__ A_log, const float* __restrict__ Dskip,
                        const float* __restrict__ out_proj_W) {
    __shared__ float op[32];
    __shared__ float ys[8][8], os[8][8];
    int tid = threadIdx.x;
    if (tid < 32) op[tid] = out_proj_W[tid];
    __syncthreads();
    int warp = tid >> 5, lane = tid & 31;
    int idx = blockIdx.x * 8 + warp;
    if (idx >= NN) return;
    int li = lane & 7;

    float ipx[4], ipz[4], cwr[4];
#pragma unroll
    for (int m = 0; m < 4; m++) {
        ipx[m] = __ldg(&in_proj_W[m * 16 + li]);
        ipz[m] = __ldg(&in_proj_W[m * 16 + 8 + li]);
        cwr[m] = __ldg(&conv_W[li * 4 + m]);
    }
    float cbr = __ldg(&conv_b[li]);
    float dtwr = __ldg(&dt_proj_W[li]);
    float dtbr = __ldg(&dt_proj_b[li]);
    float dskr = __ldg(&Dskip[li]);
    float xp0r[8], xpBr[8], xpCr[8], Asr[8];
#pragma unroll
    for (int i = 0; i < 8; i++) {
        xp0r[i] = __ldg(&x_proj_W[i * 65]);
        xpBr[i] = __ldg(&x_proj_W[i * 65 + 1 + lane]);
        xpCr[i] = __ldg(&x_proj_W[i * 65 + 33 + lane]);
        Asr[i] = -__expf(__ldg(&A_log[i * 32 + lane]));
    }

    int n = g_order[idx];
    int rl = read_length[n];
    float hst[8];
#pragma unroll
    for (int i = 0; i < 8; i++) hst[i] = 0.f;
    float c0 = 0.f, c1 = 0.f, c2 = 0.f;
    float xc = 0.f, zf = 0.f, CsLast = 0.f;
    const float4* rd4 = (const float4*)(reads + (size_t)n * LL * 4);
    float4 rd = rd4[0];

    for (int t = 0; t < rl; t++) {
        int tn = (t + 1 < rl) ? (t + 1) : t;
        float4 nxt = rd4[tn];                          // prefetch
        float xh = rd.x * ipx[0] + rd.y * ipx[1] + rd.z * ipx[2] + rd.w * ipx[3];
        float c = c0 * cwr[0] + c1 * cwr[1] + c2 * cwr[2] + xh * cwr[3] + cbr;
        c0 = c1; c1 = c2; c2 = xh;
        xc = c * sigmoidf_(c);
        if (t == rl - 1)
            zf = rd.x * ipz[0] + rd.y * ipz[1] + rd.z * ipz[2] + rd.w * ipz[3];

        float xr[8];
        float dbl0 = 0.f, Bs = 0.f, Cs = 0.f;
#pragma unroll
        for (int i = 0; i < 8; i++) {
            float xi = __shfl_sync(0xffffffffu, xc, i);
            xr[i] = xi;
            dbl0 += xi * xp0r[i];
            Bs += xi * xpBr[i];
            Cs += xi * xpCr[i];
        }
        float dr = dbl0 * dtwr + dtbr;
        float dtv = (dr > 15.f) ? dr : __logf(1.f + __expf(dr));
#pragma unroll
        for (int i = 0; i < 8; i++) {
            float dti = __shfl_sync(0xffffffffu, dtv, i);
            hst[i] = __expf(dti * Asr[i]) * hst[i] + (dti * Bs) * xr[i];
        }
        if (t == rl - 1) CsLast = Cs;
        rd = nxt;
    }
#pragma unroll
    for (int i = 0; i < 8; i++) {
        float v = hst[i] * CsLast;
#pragma unroll
        for (int off = 16; off; off >>= 1) v += __shfl_xor_sync(0xffffffffu, v, off);
        if (lane == 0) ys[warp][i] = v;
    }
    __syncwarp();
    if (lane < 8) {
        float y = ys[warp][lane] + xc * dskr;
        os[warp][lane] = y * (zf * sigmoidf_(zf));
    }
    __syncwarp();
    if (lane < 4) {
        float acc = 0.f;
#pragma unroll
        for (int i = 0; i < 8; i++) acc += os[warp][i] * op[i * 4 + lane];
        g_x2[n * 4 + lane] = acc;
    }
}

// ---------------- encoders ----------------
__global__ void k_enc(const float* __restrict__ in, const float* __restrict__ W1,
                      const float* __restrict__ b1, const float* __restrict__ W2,
                      const float* __restrict__ b2, int rows, int target_e) {
    float* outp = target_e ? g_e : g_h;
    int tid = threadIdx.x;
    int j = tid & 63, g = tid >> 6;
    float w1a[16], w1b[16], bb1[16], w2c[16];
#pragma unroll
    for (int i = 0; i < 16; i++) {
        w1a[i] = W1[i];
        w1b[i] = W1[16 + i];
        bb1[i] = b1[i];
        w2c[i] = W2[i * 64 + j];
    }
    float b2j = b2[j];
    for (int r = blockIdx.x * 4 + g; r < rows; r += gridDim.x * 4) {
        float x0 = in[r * 2], x1 = in[r * 2 + 1];
        float acc = b2j;
#pragma unroll
        for (int i = 0; i < 16; i++) {
            float hid = fmaxf(x0 * w1a[i] + x1 * w1b[i] + bb1[i], 0.f);
            acc += hid * w2c[i];
        }
        outp[r * 64 + j] = acc;
    }
}

// ---------------- per-layer node GEMM (tiled): g_hw[:, m*64:(m+1)*64] = h @ W_m + b_m ----------------
// grid (ceil(NN/64), 5), block 256, thread (tx,ty) computes 4x4 outputs
__global__ void __launch_bounds__(256)
k_hw(const float* __restrict__ gnn_W, const float* __restrict__ gnn_b, int l) {
    __shared__ float hsT[64][68];   // hsT[k][node_local]
    __shared__ float ws[64][68];    // ws[k][c]
    int tid = threadIdx.x;
    int tx = tid & 15, ty = tid >> 4;
    int n0 = blockIdx.x * 64;
    int m = blockIdx.y;
    const float* Wm = gnn_W + (size_t)(l * 6 + m) * 4096;
#pragma unroll
    for (int i = 0; i < 16; i++) {
        int idx = tid + 256 * i;
        int rr = idx >> 6, cc = idx & 63;
        ws[rr][cc] = Wm[idx];
        int n = n0 + rr;
        hsT[cc][rr] = (n < NN) ? g_h[(size_t)n * 64 + cc] : 0.f;
    }
    __syncthreads();
    float acc[4][4] = {{0.f}};
#pragma unroll 16
    for (int k = 0; k < 64; k++) {
        float4 a = *(const float4*)&hsT[k][4 * ty];
        float4 b = *(const float4*)&ws[k][4 * tx];
        acc[0][0] += a.x * b.x; acc[0][1] += a.x * b.y; acc[0][2] += a.x * b.z; acc[0][3] += a.x * b.w;
        acc[1][0] += a.y * b.x; acc[1][1] += a.y * b.y; acc[1][2] += a.y * b.z; acc[1][3] += a.y * b.w;
        acc[2][0] += a.z * b.x; acc[2][1] += a.z * b.y; acc[2][2] += a.z * b.z; acc[2][3] += a.z * b.w;
        acc[3][0] += a.w * b.x; acc[3][1] += a.w * b.y; acc[3][2] += a.w * b.z; acc[3][3] += a.w * b.w;
    }
    const float* bm = gnn_b + (size_t)(l * 6 + m) * 64;
    float4 bias = *(const float4*)&bm[4 * tx];
#pragma unroll
    for (int i = 0; i < 4; i++) {
        int n = n0 + 4 * ty + i;
        if (n >= NN) break;
        float4 r;
        r.x = acc[i][0] + bias.x;
        r.y = acc[i][1] + bias.y;
        r.z = acc[i][2] + bias.z;
        r.w = acc[i][3] + bias.w;
        *(float4*)&g_hw[(size_t)n * 320 + m * 64 + 4 * tx] = r;
    }
}

// ---------------- per-layer edge update (tiled GEMM): e += relu(e@W5 + b5 + B1h[src] + B2h[dst]) ----------------
// grid 2500, block 256; tile = 64 edges x 64 channels; EE = 2500*64 exactly
__global__ void __launch_bounds__(256)
k_edge(const int* __restrict__ src, const int* __restrict__ dst,
       const float* __restrict__ gnn_W, const float* __restrict__ gnn_b, int l) {
    __shared__ float esT[64][68];   // esT[k][edge_local]
    __shared__ float ws[64][68];    // ws[k][c]
    __shared__ int ssrc[64], sdst[64];
    int tid = threadIdx.x;
    int tx = tid & 15, ty = tid >> 4;
    int e0 = blockIdx.x * 64;
    const float* W5 = gnn_W + (size_t)(l * 6 + 5) * 4096;
#pragma unroll
    for (int i = 0; i < 16; i++) {
        int idx = tid + 256 * i;
        int rr = idx >> 6, cc = idx & 63;
        ws[rr][cc] = W5[idx];
        esT[cc][rr] = g_e[(size_t)(e0 + rr) * 64 + cc];
    }
    if (tid < 64) { ssrc[tid] = src[e0 + tid]; sdst[tid] = dst[e0 + tid]; }
    __syncthreads();
    float acc[4][4] = {{0.f}};
#pragma unroll 16
    for (int k = 0; k < 64; k++) {
        float4 a = *(const float4*)&esT[k][4 * ty];
        float4 b = *(const float4*)&ws[k][4 * tx];
        acc[0][0] += a.x * b.x; acc[0][1] += a.x * b.y; acc[0][2] += a.x * b.z; acc[0][3] += a.x * b.w;
        acc[1][0] += a.y * b.x; acc[1][1] += a.y * b.y; acc[1][2] += a.y * b.z; acc[1][3] += a.y * b.w;
        acc[2][0] += a.z * b.x; acc[2][1] += a.z * b.y; acc[2][2] += a.z * b.z; acc[2][3] += a.z * b.w;
        acc[3][0] += a.w * b.x; acc[3][1] += a.w * b.y; acc[3][2] += a.w * b.z; acc[3][3] += a.w * b.w;
    }
    const float* b5 = gnn_b + (size_t)(l * 6 + 5) * 64;
    float4 bias = *(const float4*)&b5[4 * tx];
#pragma unroll
    for (int i = 0; i < 4; i++) {
        int el = 4 * ty + i;
        int eg = e0 + el;
        int s = ssrc[el], d = sdst[el];
        float4 h1 = *(const float4*)&g_hw[(size_t)s * 320 + 192 + 4 * tx];
        float4 h2 = *(const float4*)&g_hw[(size_t)d * 320 + 256 + 4 * tx];
        float4 r;
        r.x = esT[4 * tx + 0][el] + fmaxf(acc[i][0] + bias.x + h1.x + h2.x, 0.f);
        r.y = esT[4 * tx + 1][el] + fmaxf(acc[i][1] + bias.y + h1.y + h2.y, 0.f);
        r.z = esT[4 * tx + 2][el] + fmaxf(acc[i][2] + bias.z + h1.z + h2.z, 0.f);
        r.w = esT[4 * tx + 3][el] + fmaxf(acc[i][3] + bias.w + h1.w + h2.w, 0.f);
        *(float4*)&g_e[(size_t)eg * 64 + 4 * tx] = r;
    }
}

// ---------------- fused aggregation + h update: block per node, 128 threads ----------------
__global__ void k_agg(const int* __restrict__ src, const int* __restrict__ dst) {
    __shared__ float sf[64], sb[64];
    int n = blockIdx.x;
    int tid = threadIdx.x;  // 128
    bool fwd = tid < 64;
    int j = tid & 63;
    const int* ofs = fwd ? g_ofs_in : g_ofs_out;
    const int* csr = fwd ? g_csr_in : g_csr_out;
    const int* oth = fwd ? src : dst;
    int off = fwd ? 64 : 128;
    int beg = ofs[n], end = ofs[n + 1];
    float num = 0.f, den = 0.f;
    int p = beg;
    for (; p + 3 < end; p += 4) {
        int e0 = csr[p], e1 = csr[p + 1], e2 = csr[p + 2], e3 = csr[p + 3];
        int o0 = oth[e0], o1 = oth[e1], o2 = oth[e2], o3 = oth[e3];
        float v0 = __ldg(&g_e[(size_t)e0 * 64 + j]);
        float v1 = __ldg(&g_e[(size_t)e1 * 64 + j]);
        float v2 = __ldg(&g_e[(size_t)e2 * 64 + j]);
        float v3 = __ldg(&g_e[(size_t)e3 * 64 + j]);
        float h0 = __ldg(&g_hw[(size_t)o0 * 320 + off + j]);
        float h1 = __ldg(&g_hw[(size_t)o1 * 320 + off + j]);
        float h2 = __ldg(&g_hw[(size_t)o2 * 320 + off + j]);
        float h3 = __ldg(&g_hw[(size_t)o3 * 320 + off + j]);
        float s0 = sigmoidf_(v0), s1 = sigmoidf_(v1), s2 = sigmoidf_(v2), s3 = sigmoidf_(v3);
        num += s0 * h0 + s1 * h1 + s2 * h2 + s3 * h3;
        den += (s0 + s1) + (s2 + s3);
    }
    for (; p < end; p++) {
        int e0 = csr[p];
        int o0 = oth[e0];
        float s0 = sigmoidf_(__ldg(&g_e[(size_t)e0 * 64 + j]));
        num += s0 * __ldg(&g_hw[(size_t)o0 * 320 + off + j]);
        den += s0;
    }
    (fwd ? sf : sb)[j] = num / (den + EPSV);
    __syncthreads();
    if (tid < 64) {
        float v = g_hw[(size_t)n * 320 + j] + sf[j] + sb[j];
        g_h[n * 64 + j] += fmaxf(v, 0.f);
    }
}

// ---------------- h += x2 @ base_W + base_b ----------------
__global__ void k_base(const float* __restrict__ base_W, const float* __restrict__ base_b) {
    int idx = blockIdx.x * blockDim.x + threadIdx.x;
    if (idx < NN * 64) {
        int n = idx >> 6, j = idx & 63;
        float v = g_x2[n * 4 + 0] * base_W[j] + g_x2[n * 4 + 1] * base_W[64 + j]
                + g_x2[n * 4 + 2] * base_W[128 + j] + g_x2[n * 4 + 3] * base_W[192 + j] + base_b[j];
        g_h[idx] += v;
    }
}

// ---------------- prediction head, stage 1: per-node projections (tiled GEMM, 2 matrices) ----------------
__global__ void __launch_bounds__(256)
k_prednode(const float* __restrict__ Wp1) {
    __shared__ float hsT[64][68];
    __shared__ float ws[64][68];
    int tid = threadIdx.x;
    int tx = tid & 15, ty = tid >> 4;
    int n0 = blockIdx.x * 64;
    int m = blockIdx.y;   // 0: src-part, 1: dst-part
    const float* Wm = Wp1 + (size_t)m * 4096;
#pragma unroll
    for (int i = 0; i < 16; i++) {
        int idx = tid + 256 * i;
        int rr = idx >> 6, cc = idx & 63;
        ws[rr][cc] = Wm[idx];
        int n = n0 + rr;
        hsT[cc][rr] = (n < NN) ? g_h[(size_t)n * 64 + cc] : 0.f;
    }
    __syncthreads();
    float acc[4][4] = {{0.f}};
#pragma unroll 16
    for (int k = 0; k < 64; k++) {
        float4 a = *(const float4*)&hsT[k][4 * ty];
        float4 b = *(const float4*)&ws[k][4 * tx];
        acc[0][0] += a.x * b.x; acc[0][1] += a.x * b.y; acc[0][2] += a.x * b.z; acc[0][3] += a.x * b.w;
        acc[1][0] += a.y * b.x; acc[1][1] += a.y * b.y; acc[1][2] += a.y * b.z; acc[1][3] += a.y * b.w;
        acc[2][0] += a.z * b.x; acc[2][1] += a.z * b.y; acc[2][2] += a.z * b.z; acc[2][3] += a.z * b.w;
        acc[3][0] += a.w * b.x; acc[3][1] += a.w * b.y; acc[3][2] += a.w * b.z; acc[3][3] += a.w * b.w;
    }
#pragma unroll
    for (int i = 0; i < 4; i++) {
        int n = n0 + 4 * ty + i;
        if (n >= NN) break;
        float4 r;
        r.x = acc[i][0]; r.y = acc[i][1]; r.z = acc[i][2]; r.w = acc[i][3];
        *(float4*)&g_hw[(size_t)n * 320 + m * 64 + 4 * tx] = r;
    }
}

// ---------------- prediction head, stage 2: per-edge (tiled GEMM + reduce) ----------------
__global__ void __launch_bounds__(256)
k_prededge(const int* __restrict__ src, const int* __restrict__ dst,
           const float* __restrict__ Wp1, const float* __restrict__ bp1,
           const float* __restrict__ Wp2, const float* __restrict__ bp2,
           float* __restrict__ out) {
    __shared__ float esT[64][68];
    __shared__ float ws[64][68];
    __shared__ int ssrc[64], sdst[64];
    __shared__ float part[64][17];   // per-edge partial sums by tx (padded)
    int tid = threadIdx.x;
    int tx = tid & 15, ty = tid >> 4;
    int e0 = blockIdx.x * 64;
    const float* Wc = Wp1 + (size_t)128 * 64;
#pragma unroll
    for (int i = 0; i < 16; i++) {
        int idx = tid + 256 * i;
        int rr = idx >> 6, cc = idx & 63;
        ws[rr][cc] = Wc[idx];
        esT[cc][rr] = g_e[(size_t)(e0 + rr) * 64 + cc];
    }
    if (tid < 64) { ssrc[tid] = src[e0 + tid]; sdst[tid] = dst[e0 + tid]; }
    __syncthreads();
    float acc[4][4] = {{0.f}};
#pragma unroll 16
    for (int k = 0; k < 64; k++) {
        float4 a = *(const float4*)&esT[k][4 * ty];
        float4 b = *(const float4*)&ws[k][4 * tx];
        acc[0][0] += a.x * b.x; acc[0][1] += a.x * b.y; acc[0][2] += a.x * b.z; acc[0][3] += a.x * b.w;
        acc[1][0] += a.y * b.x; acc[1][1] += a.y * b.y; acc[1][2] += a.y * b.z; acc[1][3] += a.y * b.w;
        acc[2][0] += a.z * b.x; acc[2][1] += a.z * b.y; acc[2][2] += a.z * b.z; acc[2][3] += a.z * b.w;
        acc[3][0] += a.w * b.x; acc[3][1] += a.w * b.y; acc[3][2] += a.w * b.z; acc[3][3] += a.w * b.w;
    }
    float4 bias = *(const float4*)&bp1[4 * tx];
    float4 w2 = *(const float4*)&Wp2[4 * tx];
    float bp2v = bp2[0];
#pragma unroll
    for (int i = 0; i < 4; i++) {
        int el = 4 * ty + i;
        int s = ssrc[el], d = sdst[el];
        float4 h1 = *(const float4*)&g_hw[(size_t)s * 320 + 4 * tx];
        float4 h2 = *(const float4*)&g_hw[(size_t)d * 320 + 64 + 4 * tx];
        float p = fmaxf(acc[i][0] + bias.x + h1.x + h2.x, 0.f) * w2.x
                + fmaxf(acc[i][1] + bias.y + h1.y + h2.y, 0.f) * w2.y
                + fmaxf(acc[i][2] + bias.z + h1.z + h2.z, 0.f) * w2.z
                + fmaxf(acc[i][3] + bias.w + h1.w + h2.w, 0.f) * w2.w;
        part[el][tx] = p;
    }
    __syncthreads();
    // 64 threads each reduce one edge's 16 partials
    if (tid < 64) {
        float s = 0.f;
#pragma unroll
        for (int q = 0; q < 16; q++) s += part[tid][q];
        out[e0 + tid] = s + bp2v;
    }
}

// ---------------- launch ----------------
extern "C" void kernel_launch(void* const* d_in, const int* in_sizes, int n_in,
                              void* d_out, int out_size) {
    const float* x        = (const float*)d_in[0];
    const float* e_in     = (const float*)d_in[1];
    const float* reads    = (const float*)d_in[2];
    const int*   src      = (const int*)d_in[3];
    const int*   dst      = (const int*)d_in[4];
    const int*   rl       = (const int*)d_in[5];
    const float* W1n      = (const float*)d_in[6];
    const float* b1n      = (const float*)d_in[7];
    const float* W2n      = (const float*)d_in[8];
    const float* b2n      = (const float*)d_in[9];
    const float* W1e      = (const float*)d_in[10];
    const float* b1e      = (const float*)d_in[11];
    const float* W2e      = (const float*)d_in[12];
    const float* b2e      = (const float*)d_in[13];
    const float* gnn_W    = (const float*)d_in[14];
    const float* gnn_b    = (const float*)d_in[15];
    const float* in_projW = (const float*)d_in[16];
    const float* conv_W   = (const float*)d_in[17];
    const float* conv_b   = (const float*)d_in[18];
    const float* x_projW  = (const float*)d_in[19];
    const float* dt_projW = (const float*)d_in[20];
    const float* dt_projb = (const float*)d_in[21];
    const float* A_log    = (const float*)d_in[22];
    const float* Dskip    = (const float*)d_in[23];
    const float* out_projW= (const float*)d_in[24];
    const float* base_W   = (const float*)d_in[25];
    const float* base_b   = (const float*)d_in[26];
    const float* Wp1      = (const float*)d_in[27];
    const float* bp1      = (const float*)d_in[28];
    const float* Wp2      = (const float*)d_in[29];
    const float* bp2      = (const float*)d_in[30];
    float* out = (float*)d_out;

    static cudaStream_t s1 = nullptr, s2 = nullptr;
    static cudaEvent_t evFork = nullptr, evCsr = nullptr, evMamba = nullptr;
    if (s1 == nullptr) {
        cudaStreamCreateWithFlags(&s1, cudaStreamNonBlocking);
        cudaStreamCreateWithFlags(&s2, cudaStreamNonBlocking);
        cudaEventCreateWithFlags(&evFork, cudaEventDisableTiming);
        cudaEventCreateWithFlags(&evCsr, cudaEventDisableTiming);
        cudaEventCreateWithFlags(&evMamba, cudaEventDisableTiming);
    }

    dim3 hwGrid((NN + 63) / 64, 5);
    dim3 pnGrid((NN + 63) / 64, 2);

    // main stream: first 4 kernels (idx 3 = GEMM k_edge l0 -> ncu sample)
    k_enc<<<512, 256>>>(x, W1n, b1n, W2n, b2n, NN, 0);               // 0
    k_enc<<<2048, 256>>>(e_in, W1e, b1e, W2e, b2e, EE, 1);           // 1
    k_hw<<<hwGrid, 256>>>(gnn_W, gnn_b, 0);                          // 2
    k_edge<<<EE / 64, 256>>>(src, dst, gnn_W, gnn_b, 0);             // 3 <- profiled
    cudaEventRecord(evFork, 0);

    // side branch 1: CSR build
    cudaStreamWaitEvent(s1, evFork, 0);
    k_zero_deg<<<(NN + 255) / 256, 256, 0, s1>>>();
    k_hist<<<(EE + 255) / 256, 256, 0, s1>>>(src, dst);
    k_scan<<<1, 1024, 0, s1>>>();
    k_fill<<<(EE + 255) / 256, 256, 0, s1>>>(src, dst);
    k_sortcsr<<<(2 * NN * 32 + 255) / 256, 256, 0, s1>>>();
    cudaEventRecord(evCsr, s1);

    // side branch 2: mamba
    cudaStreamWaitEvent(s2, evFork, 0);
    k_rlscanplace<<<1, 256, 0, s2>>>(rl);
    k_mamba<<<1250, 256, 0, s2>>>(reads, rl, in_projW, conv_W, conv_b,
                                  x_projW, dt_projW, dt_projb, A_log, Dskip, out_projW);
    cudaEventRecord(evMamba, s2);

    // main: layer 0 aggregation needs CSR
    cudaStreamWaitEvent(0, evCsr, 0);
    k_agg<<<NN, 128>>>(src, dst);

    for (int l = 1; l < NLAYERS; l++) {
        k_hw<<<hwGrid, 256>>>(gnn_W, gnn_b, l);
        k_edge<<<EE / 64, 256>>>(src, dst, gnn_W, gnn_b, l);
        k_agg<<<NN, 128>>>(src, dst);
    }

    // base add needs mamba result
    cudaStreamWaitEvent(0, evMamba, 0);
    k_base<<<(NN * 64 + 255) / 256, 256>>>(base_W, base_b);
    k_prednode<<<pnGrid, 256>>>(Wp1);
    k_prededge<<<EE / 64, 256>>>(src, dst, Wp1, bp1, Wp2, bp2, out);
}